// round 12
// baseline (speedup 1.0000x reference)
#include <cuda_runtime.h>
#include <cuda_bf16.h>
#include <math.h>

#define MAXN 50000
#define MAXE 800000
#define D    128
#define BN_EPS 1e-5f

// ---------------- scratch (static __device__ — no allocations) -------------
__device__ __align__(16) __nv_bfloat16 g_hb0[MAXN * D];
__device__ __align__(16) __nv_bfloat16 g_hb1[MAXN * D];
__device__ __align__(16) __nv_bfloat16 g_hb2[MAXN * D];
__device__ __align__(16) __nv_bfloat16 g_wb[114688];     // Wg|Wc1|Wc2 bf16
__device__ __align__(16) unsigned int g_zb[MAXN * 64];   // z as bf16x2 pairs
__device__ float g_norm[MAXN];
__device__ int   g_deg[MAXN];
__device__ int   g_rowptr[MAXN + 1];
__device__ int   g_cursor[MAXN];
__device__ __align__(16) uint2 g_csredge[MAXE];          // {src*16, norm bits}
__device__ volatile int g_scanflag[64];                  // chained-scan prefixes
__device__ float g_bnacc[512];
__device__ float g_colsum[128];

// ---------------- init: zero accumulators + convert weights ----------------
__global__ void init_kernel(int n, const float* __restrict__ Wg,
                            const float* __restrict__ Wc1,
                            const float* __restrict__ Wc2) {
    int i = blockIdx.x * blockDim.x + threadIdx.x;
    if (i < n)   g_deg[i] = 0;
    if (i < 512) g_bnacc[i] = 0.f;
    if (i < 128) g_colsum[i] = 0.f;
    if (i < 64)  g_scanflag[i] = -1;
    if (i < 16384)       g_wb[i] = __float2bfloat16(Wg[i]);
    else if (i < 65536)  g_wb[i] = __float2bfloat16(Wc1[i - 16384]);
    else if (i < 114688) g_wb[i] = __float2bfloat16(Wc2[i - 65536]);
}

// ---------------- degree histogram (2 edges/thread) -------------------------
__global__ void count_deg_kernel(const int* __restrict__ dst, int e) {
    int i = blockIdx.x * blockDim.x + threadIdx.x;
    int half = e >> 1;
    if (i < half) {
        int2 d = ((const int2*)dst)[i];
        atomicAdd(&g_deg[d.x], 1);
        atomicAdd(&g_deg[d.y], 1);
    }
    if (i == 0 && (e & 1)) atomicAdd(&g_deg[dst[e - 1]], 1);
}

// ---------------- fused chained scan (blocks co-resident: nb <= 64 <= #SM) --
__global__ void scan_fused_kernel(int n, int e, int nb) {
    __shared__ int sm[1024];
    __shared__ int s_pref;
    int t = threadIdx.x;
    int b = blockIdx.x;
    int i = b * 1024 + t;
    int v = (i < n) ? g_deg[i] : 0;
    if (i < n) g_norm[i] = rsqrtf((float)(v > 0 ? v : 1));
    sm[t] = v;
    __syncthreads();
    #pragma unroll
    for (int off = 1; off < 1024; off <<= 1) {
        int x = sm[t];
        if (t >= off) x += sm[t - off];
        __syncthreads();
        sm[t] = x;
        __syncthreads();
    }
    int incl = sm[t];
    int tot  = sm[1023];
    if (t == 0) {
        int pref = 0;
        if (b > 0) while ((pref = g_scanflag[b - 1]) < 0) {}
        g_scanflag[b] = pref + tot;     // single-word publish
        s_pref = pref;
    }
    __syncthreads();
    if (i < n) {
        int r = s_pref + incl - v;
        g_rowptr[i] = r;
        g_cursor[i] = r;
    }
    if (b == nb - 1 && t == 0) g_rowptr[n] = e;
}

// ---------------- CSR scatter: fused edge records {src*16, norm(src)} ------
__global__ void scatter_kernel(const int* __restrict__ src,
                               const int* __restrict__ dst, int e) {
    int i = blockIdx.x * blockDim.x + threadIdx.x;
    int half = e >> 1;
    if (i < half) {
        int2 d = ((const int2*)dst)[i];
        int2 s = ((const int2*)src)[i];
        int p0 = atomicAdd(&g_cursor[d.x], 1);
        g_csredge[p0] = make_uint2((unsigned)(s.x * 16),
                                   __float_as_uint(g_norm[s.x]));
        int p1 = atomicAdd(&g_cursor[d.y], 1);
        g_csredge[p1] = make_uint2((unsigned)(s.y * 16),
                                   __float_as_uint(g_norm[s.y]));
    }
    if (i == 0 && (e & 1)) {
        int s = src[e - 1];
        int p = atomicAdd(&g_cursor[dst[e - 1]], 1);
        g_csredge[p] = make_uint2((unsigned)(s * 16),
                                  __float_as_uint(g_norm[s]));
    }
}

// ---------------- half-warp-per-node SpMM (uint4 rows, fused edges) ---------
// hout[v] = norm[v] * sum_{s in CSR[v]} norm[s] * hin[s]
__global__ __launch_bounds__(256)
void spmm_kernel(const uint4* __restrict__ hin,
                 uint4* __restrict__ hout, int n) {
    int hw   = threadIdx.x >> 4;          // half-warp slot 0..15
    int node = blockIdx.x * 16 + hw;
    int lane = threadIdx.x & 15;
    if (node >= n) return;
    int beg = g_rowptr[node], end = g_rowptr[node + 1];
    const uint4* hp = hin + lane;         // pre-biased by lane
    float a0 = 0.f, a1 = 0.f, a2 = 0.f, a3 = 0.f;
    float a4 = 0.f, a5 = 0.f, a6 = 0.f, a7 = 0.f;
    #pragma unroll 4
    for (int e = beg; e < end; e++) {
        uint2 em = __ldg(&g_csredge[e]);   // broadcast LDG.64
        uint4 p  = __ldg(&hp[em.x]);       // LDG.128 feature row slice
        float w  = __uint_as_float(em.y);
        float2 f0 = __bfloat1622float2(*(__nv_bfloat162*)&p.x);
        float2 f1 = __bfloat1622float2(*(__nv_bfloat162*)&p.y);
        float2 f2 = __bfloat1622float2(*(__nv_bfloat162*)&p.z);
        float2 f3 = __bfloat1622float2(*(__nv_bfloat162*)&p.w);
        a0 = fmaf(f0.x, w, a0);  a1 = fmaf(f0.y, w, a1);
        a2 = fmaf(f1.x, w, a2);  a3 = fmaf(f1.y, w, a3);
        a4 = fmaf(f2.x, w, a4);  a5 = fmaf(f2.y, w, a5);
        a6 = fmaf(f3.x, w, a6);  a7 = fmaf(f3.y, w, a7);
    }
    float nv = g_norm[node];
    __nv_bfloat162 o0 = __float22bfloat162_rn(make_float2(a0 * nv, a1 * nv));
    __nv_bfloat162 o1 = __float22bfloat162_rn(make_float2(a2 * nv, a3 * nv));
    __nv_bfloat162 o2 = __float22bfloat162_rn(make_float2(a4 * nv, a5 * nv));
    __nv_bfloat162 o3 = __float22bfloat162_rn(make_float2(a6 * nv, a7 * nv));
    hout[node * 16 + lane] = make_uint4(*(unsigned*)&o0, *(unsigned*)&o1,
                                        *(unsigned*)&o2, *(unsigned*)&o3);
}

// ---------------- tensor-core GEMM helpers ----------------------------------
__device__ __forceinline__ void ldsm4(unsigned (&r)[4], unsigned addr) {
    asm volatile("ldmatrix.sync.aligned.m8n8.x4.shared.b16 {%0,%1,%2,%3}, [%4];"
        : "=r"(r[0]), "=r"(r[1]), "=r"(r[2]), "=r"(r[3]) : "r"(addr));
}
__device__ __forceinline__ void ldsm4t(unsigned (&r)[4], unsigned addr) {
    asm volatile("ldmatrix.sync.aligned.m8n8.x4.trans.shared.b16 {%0,%1,%2,%3}, [%4];"
        : "=r"(r[0]), "=r"(r[1]), "=r"(r[2]), "=r"(r[3]) : "r"(addr));
}
__device__ __forceinline__ void mma_bf16(float (&c)[4], const unsigned (&a)[4],
                                         unsigned b0, unsigned b1) {
    asm volatile("mma.sync.aligned.m16n8k16.row.col.f32.bf16.bf16.f32 "
        "{%0,%1,%2,%3}, {%4,%5,%6,%7}, {%8,%9}, {%0,%1,%2,%3};"
        : "+f"(c[0]), "+f"(c[1]), "+f"(c[2]), "+f"(c[3])
        : "r"(a[0]), "r"(a[1]), "r"(a[2]), "r"(a[3]), "r"(b0), "r"(b1));
}

// C = act([A|...] @ Wb) -> bf16x2 packed output.
// Af non-null: A is fp32 (gating path), converted during smem load.
// statacc non-null: fused BN stats (per-col sum / sumsq of pre-rounding fp32).
#define A_STRIDE 56
#define B_STRIDE 136
__global__ __launch_bounds__(256, 2)
void gemm_bf16_kernel(const __nv_bfloat16* __restrict__ A0,
                      const __nv_bfloat16* __restrict__ A1,
                      const __nv_bfloat16* __restrict__ A2,
                      const float* __restrict__ Af,
                      const __nv_bfloat16* __restrict__ Wb,
                      const float* __restrict__ bias,
                      unsigned int* __restrict__ outb,
                      float* __restrict__ statacc,
                      int nrows, int ktiles, int act) {
    __shared__ __align__(16) unsigned short As[128 * A_STRIDE];
    __shared__ __align__(16) unsigned short Bs[32 * B_STRIDE];
    __shared__ float smstat[256];

    int tid  = threadIdx.x;
    int lane = tid & 31;
    int wid  = tid >> 5;
    int m_warp = (wid >> 1) * 32;
    int n_warp = (wid & 1) * 64;
    int r0 = blockIdx.x * 128;

    unsigned as_base = (unsigned)__cvta_generic_to_shared(As);
    unsigned bs_base = (unsigned)__cvta_generic_to_shared(Bs);

    float acc[2][8][4];
    #pragma unroll
    for (int mt = 0; mt < 2; mt++)
        #pragma unroll
        for (int nt = 0; nt < 8; nt++)
            #pragma unroll
            for (int k = 0; k < 4; k++) acc[mt][nt][k] = 0.f;

    for (int kt = 0; kt < ktiles; kt++) {
        int seg = kt >> 2;
        const __nv_bfloat16* Ap = (seg == 0) ? A0 : ((seg == 1) ? A1 : A2);
        int kk = (kt & 3) * 32;

        // A tile [128 x 32] bf16 (convert from fp32 if Af path)
        #pragma unroll
        for (int it = 0; it < 2; it++) {
            int idx = tid + it * 256;
            int row = idx >> 2;
            int ch  = idx & 3;
            int gr  = r0 + row;
            uint4 v = make_uint4(0u, 0u, 0u, 0u);
            if (Af) {
                if (gr < nrows) {
                    float4 u0 = *(const float4*)(Af + gr * 128 + kk + ch * 8);
                    float4 u1 = *(const float4*)(Af + gr * 128 + kk + ch * 8 + 4);
                    __nv_bfloat162 p0 = __float22bfloat162_rn(make_float2(u0.x, u0.y));
                    __nv_bfloat162 p1 = __float22bfloat162_rn(make_float2(u0.z, u0.w));
                    __nv_bfloat162 p2 = __float22bfloat162_rn(make_float2(u1.x, u1.y));
                    __nv_bfloat162 p3 = __float22bfloat162_rn(make_float2(u1.z, u1.w));
                    v = make_uint4(*(unsigned*)&p0, *(unsigned*)&p1,
                                   *(unsigned*)&p2, *(unsigned*)&p3);
                }
            } else if (gr < nrows) {
                v = *(const uint4*)(Ap + gr * 128 + kk + ch * 8);
            }
            *(uint4*)(As + row * A_STRIDE + ch * 8) = v;
        }
        // B tile [32 x 128] bf16
        #pragma unroll
        for (int it = 0; it < 2; it++) {
            int idx = tid + it * 256;
            int row = idx >> 4;
            int ch  = idx & 15;
            uint4 v = *(const uint4*)(Wb + (kt * 32 + row) * 128 + ch * 8);
            *(uint4*)(Bs + row * B_STRIDE + ch * 8) = v;
        }
        __syncthreads();

        #pragma unroll
        for (int ksub = 0; ksub < 2; ksub++) {
            unsigned a[2][4];
            #pragma unroll
            for (int mt = 0; mt < 2; mt++) {
                unsigned addr = as_base +
                    ((m_warp + mt * 16 + (lane & 15)) * A_STRIDE +
                     ksub * 16 + (lane >> 4) * 8) * 2;
                ldsm4(a[mt], addr);
            }
            unsigned b[4][4];
            #pragma unroll
            for (int nt2 = 0; nt2 < 4; nt2++) {
                unsigned addr = bs_base +
                    ((ksub * 16 + (lane & 15)) * B_STRIDE +
                     n_warp + nt2 * 16 + (lane >> 4) * 8) * 2;
                ldsm4t(b[nt2], addr);
            }
            #pragma unroll
            for (int mt = 0; mt < 2; mt++)
                #pragma unroll
                for (int nt = 0; nt < 8; nt++)
                    mma_bf16(acc[mt][nt], a[mt],
                             b[nt >> 1][(nt & 1) * 2],
                             b[nt >> 1][(nt & 1) * 2 + 1]);
        }
        __syncthreads();
    }

    // ---------------- epilogue -------------------------------------------
    int g  = lane >> 2;
    int t4 = lane & 3;
    if (statacc) {
        smstat[tid] = 0.f;
        __syncthreads();
    }
    #pragma unroll
    for (int mt = 0; mt < 2; mt++) {
        int row0 = r0 + m_warp + mt * 16 + g;
        bool v0 = row0 < nrows;
        bool v1 = row0 + 8 < nrows;
        #pragma unroll
        for (int nt = 0; nt < 8; nt++) {
            int col = n_warp + nt * 8 + 2 * t4;
            float c0 = acc[mt][nt][0], c1 = acc[mt][nt][1];
            float c2 = acc[mt][nt][2], c3 = acc[mt][nt][3];
            if (act) {
                float b0 = bias[col], b1 = bias[col + 1];
                c0 = 1.f / (1.f + __expf(-(c0 + b0)));
                c1 = 1.f / (1.f + __expf(-(c1 + b1)));
                c2 = 1.f / (1.f + __expf(-(c2 + b0)));
                c3 = 1.f / (1.f + __expf(-(c3 + b1)));
            }
            if (statacc) {
                float a0 = v0 ? c0 : 0.f, a1 = v0 ? c1 : 0.f;
                float a2 = v1 ? c2 : 0.f, a3 = v1 ? c3 : 0.f;
                float s0 = a0 + a2, s1 = a1 + a3;
                float q0 = a0 * a0 + a2 * a2, q1 = a1 * a1 + a3 * a3;
                #pragma unroll
                for (int m = 4; m < 32; m <<= 1) {
                    s0 += __shfl_xor_sync(0xffffffffu, s0, m);
                    s1 += __shfl_xor_sync(0xffffffffu, s1, m);
                    q0 += __shfl_xor_sync(0xffffffffu, q0, m);
                    q1 += __shfl_xor_sync(0xffffffffu, q1, m);
                }
                if (g == 0) {
                    atomicAdd(&smstat[col], s0);
                    atomicAdd(&smstat[col + 1], s1);
                    atomicAdd(&smstat[128 + col], q0);
                    atomicAdd(&smstat[128 + col + 1], q1);
                }
            }
            if (v0) {
                __nv_bfloat162 p = __float22bfloat162_rn(make_float2(c0, c1));
                outb[row0 * 64 + (col >> 1)] = *(unsigned*)&p;
            }
            if (v1) {
                __nv_bfloat162 p = __float22bfloat162_rn(make_float2(c2, c3));
                outb[(row0 + 8) * 64 + (col >> 1)] = *(unsigned*)&p;
            }
        }
    }
    if (statacc) {
        __syncthreads();
        atomicAdd(&statacc[tid], smstat[tid]);
    }
}

// ---------------- BN apply + ReLU (bf16 z in, optional bf16 out, colsum) ----
__global__ void bn_apply_kernel(const unsigned int* __restrict__ z2,
                                unsigned int* __restrict__ hout2,
                                const float* __restrict__ acc,
                                const float* __restrict__ gamma,
                                const float* __restrict__ beta,
                                int n, int docol) {
    int cp  = threadIdx.x & 63;
    int sub = threadIdx.x >> 6;
    int c0 = cp * 2, c1 = c0 + 1;
    float inv_n = 1.f / (float)n;
    float mu0 = acc[c0] * inv_n, mu1 = acc[c1] * inv_n;
    float va0 = acc[128 + c0] * inv_n - mu0 * mu0;
    float va1 = acc[128 + c1] * inv_n - mu1 * mu1;
    float s0 = rsqrtf(va0 + BN_EPS) * gamma[c0];
    float s1 = rsqrtf(va1 + BN_EPS) * gamma[c1];
    float h0 = beta[c0] - mu0 * s0;
    float h1 = beta[c1] - mu1 * s1;
    int r0 = blockIdx.x * 128;
    int r1 = min(r0 + 128, n);
    float cs0 = 0.f, cs1 = 0.f;
    for (int r = r0 + sub; r < r1; r += 4) {
        unsigned p = z2[r * 64 + cp];
        float2 f = __bfloat1622float2(*(__nv_bfloat162*)&p);
        float v0 = fmaxf(fmaf(f.x, s0, h0), 0.f);
        float v1 = fmaxf(fmaf(f.y, s1, h1), 0.f);
        if (hout2) {
            __nv_bfloat162 o = __float22bfloat162_rn(make_float2(v0, v1));
            hout2[r * 64 + cp] = *(unsigned*)&o;
        }
        cs0 += v0;
        cs1 += v1;
    }
    if (docol) {
        atomicAdd(&g_colsum[c0], cs0);
        atomicAdd(&g_colsum[c1], cs1);
    }
}

// ---------------- readout: out = colmean(h) @ Wd + bd -----------------------
__global__ void final_kernel(const float* __restrict__ Wd,
                             const float* __restrict__ bd,
                             float* __restrict__ out, int n) {
    int j = threadIdx.x;
    float inv_n = 1.f / (float)n;
    float acc = bd[j];
    #pragma unroll 4
    for (int c = 0; c < D; c++)
        acc = fmaf(__ldg(&g_colsum[c]) * inv_n, Wd[c * 256 + j], acc);
    out[j] = acc;
}

// ---------------- launch ----------------------------------------------------
extern "C" void kernel_launch(void* const* d_in, const int* in_sizes, int n_in,
                              void* d_out, int out_size) {
    const float* features = (const float*)d_in[0];
    const int*   src      = (const int*)  d_in[1];
    const int*   dst      = (const int*)  d_in[2];
    const float* Wg  = (const float*)d_in[3];
    const float* bg  = (const float*)d_in[4];
    const float* Wc1 = (const float*)d_in[5];
    const float* g1  = (const float*)d_in[6];
    const float* b1  = (const float*)d_in[7];
    const float* Wc2 = (const float*)d_in[8];
    const float* g2  = (const float*)d_in[9];
    const float* b2  = (const float*)d_in[10];
    const float* Wd  = (const float*)d_in[11];
    const float* bd  = (const float*)d_in[12];
    float* out = (float*)d_out;

    int N = in_sizes[0] / D;
    int E = in_sizes[1];

    void* p;
    __nv_bfloat16 *hb0, *hb1, *hb2, *wb;
    unsigned int* zb;
    float* bnacc;
    cudaGetSymbolAddress(&p, g_hb0);   hb0 = (__nv_bfloat16*)p;
    cudaGetSymbolAddress(&p, g_hb1);   hb1 = (__nv_bfloat16*)p;
    cudaGetSymbolAddress(&p, g_hb2);   hb2 = (__nv_bfloat16*)p;
    cudaGetSymbolAddress(&p, g_wb);    wb  = (__nv_bfloat16*)p;
    cudaGetSymbolAddress(&p, g_zb);    zb  = (unsigned int*)p;
    cudaGetSymbolAddress(&p, g_bnacc); bnacc = (float*)p;

    int gb  = (N + 127) / 128;
    int bnb = (N + 127) / 128;
    int spb = (N + 15) / 16;
    int nsb = (N + 1023) / 1024;
    int eb2 = ((E >> 1) + 255) / 256;

    // fork/join: run the graph-structure chain concurrently with the gating
    // GEMM. Streams/events are created+destroyed per call (no device mem).
    cudaStream_t s1;
    cudaStreamCreateWithFlags(&s1, cudaStreamNonBlocking);
    cudaEvent_t e0, e1;
    cudaEventCreateWithFlags(&e0, cudaEventDisableTiming);
    cudaEventCreateWithFlags(&e1, cudaEventDisableTiming);

    // init on main stream (weights for GEMM + zeroed deg/flags for setup)
    init_kernel<<<448, 256>>>(N, Wg, Wc1, Wc2);
    cudaEventRecord(e0, 0);
    cudaStreamWaitEvent(s1, e0, 0);

    // setup chain on side stream
    count_deg_kernel<<<eb2, 256, 0, s1>>>(dst, E);
    scan_fused_kernel<<<nsb, 1024, 0, s1>>>(N, E, nsb);
    scatter_kernel<<<eb2, 256, 0, s1>>>(src, dst, E);
    cudaEventRecord(e1, s1);

    // gating GEMM on main stream, concurrent with setup chain
    gemm_bf16_kernel<<<gb, 256>>>(nullptr, nullptr, nullptr, features, wb, bg,
                                  (unsigned int*)hb0, nullptr, N, 4, 1);

    // join: spmm needs both the gating output and the CSR structure
    cudaStreamWaitEvent(0, e1, 0);

    // ---- layer 1 ----
    spmm_kernel<<<spb, 256>>>((const uint4*)hb0, (uint4*)hb1, N);
    spmm_kernel<<<spb, 256>>>((const uint4*)hb1, (uint4*)hb2, N);
    gemm_bf16_kernel<<<gb, 256>>>(hb0, hb1, hb2, nullptr, wb + 16384, nullptr,
                                  zb, bnacc, N, 12, 0);
    bn_apply_kernel<<<bnb, 256>>>(zb, (unsigned int*)hb0, bnacc, g1, b1, N, 0);

    // ---- layer 2 ----
    spmm_kernel<<<spb, 256>>>((const uint4*)hb0, (uint4*)hb1, N);
    spmm_kernel<<<spb, 256>>>((const uint4*)hb1, (uint4*)hb2, N);
    gemm_bf16_kernel<<<gb, 256>>>(hb0, hb1, hb2, nullptr, wb + 65536, nullptr,
                                  zb, bnacc + 256, N, 12, 0);
    bn_apply_kernel<<<bnb, 256>>>(zb, nullptr, bnacc + 256, g2, b2, N, 1);

    // readout
    final_kernel<<<1, 256>>>(Wd, bd, out, N);

    cudaEventDestroy(e0);
    cudaEventDestroy(e1);
    cudaStreamDestroy(s1);
}

// round 14
// speedup vs baseline: 1.0238x; 1.0238x over previous
#include <cuda_runtime.h>
#include <cuda_bf16.h>
#include <math.h>

#define MAXN 50000
#define MAXE 800000
#define D    128
#define BN_EPS 1e-5f

// ---------------- scratch (static __device__ — no allocations) -------------
__device__ __align__(16) __nv_bfloat16 g_hb0[MAXN * D];
__device__ __align__(16) __nv_bfloat16 g_hb1[MAXN * D];
__device__ __align__(16) __nv_bfloat16 g_hb2[MAXN * D];
__device__ __align__(16) __nv_bfloat16 g_wb[114688];     // Wg|Wc1|Wc2 bf16
__device__ __align__(16) unsigned int g_zb[MAXN * 64];   // z as bf16x2 pairs
__device__ float g_norm[MAXN];
__device__ int   g_deg[MAXN];
__device__ int   g_rowptr[MAXN + 1];
__device__ int   g_cursor[MAXN];
__device__ __align__(16) uint2 g_csredge[MAXE];          // {src*16, norm bits}
__device__ int   g_blocksum[64];
__device__ float g_bnacc[512];
__device__ float g_colsum[128];

// ---------------- zero degrees (side-stream head) ----------------------------
__global__ void zero_deg_kernel(int n) {
    int i = blockIdx.x * blockDim.x + threadIdx.x;
    if (i < n) g_deg[i] = 0;
}

// ---------------- init: zero accumulators + convert weights (main stream) ---
__global__ void init_kernel(const float* __restrict__ Wg,
                            const float* __restrict__ Wc1,
                            const float* __restrict__ Wc2) {
    int i = blockIdx.x * blockDim.x + threadIdx.x;
    if (i < 512) g_bnacc[i] = 0.f;
    if (i < 128) g_colsum[i] = 0.f;
    if (i < 16384)       g_wb[i] = __float2bfloat16(Wg[i]);
    else if (i < 65536)  g_wb[i] = __float2bfloat16(Wc1[i - 16384]);
    else if (i < 114688) g_wb[i] = __float2bfloat16(Wc2[i - 65536]);
}

// ---------------- degree histogram (2 edges/thread) -------------------------
__global__ void count_deg_kernel(const int* __restrict__ dst, int e) {
    int i = blockIdx.x * blockDim.x + threadIdx.x;
    int half = e >> 1;
    if (i < half) {
        int2 d = ((const int2*)dst)[i];
        atomicAdd(&g_deg[d.x], 1);
        atomicAdd(&g_deg[d.y], 1);
    }
    if (i == 0 && (e & 1)) atomicAdd(&g_deg[dst[e - 1]], 1);
}

// ---------------- scan phase A ----------------------------------------------
__global__ void scanA_kernel(int n) {
    __shared__ int sm[1024];
    int t = threadIdx.x;
    int i = blockIdx.x * 1024 + t;
    int v = (i < n) ? g_deg[i] : 0;
    if (i < n) g_norm[i] = rsqrtf((float)(v > 0 ? v : 1));
    sm[t] = v;
    __syncthreads();
    #pragma unroll
    for (int off = 1; off < 1024; off <<= 1) {
        int x = sm[t];
        if (t >= off) x += sm[t - off];
        __syncthreads();
        sm[t] = x;
        __syncthreads();
    }
    if (i < n) g_rowptr[i] = sm[t] - v;
    if (t == 1023) g_blocksum[blockIdx.x] = sm[t];
}

// ---------------- scan phase C ----------------------------------------------
__global__ void scanC_kernel(int n, int e, int nb) {
    __shared__ int pref[64];
    int t = threadIdx.x;
    if (t < 64) {
        int s = 0;
        for (int j = 0; j < t && j < nb; j++) s += g_blocksum[j];
        pref[t] = s;
    }
    __syncthreads();
    int i = blockIdx.x * blockDim.x + t;
    if (i < n) {
        int r = g_rowptr[i] + pref[i >> 10];
        g_rowptr[i] = r;
        g_cursor[i] = r;
    }
    if (i == 0) g_rowptr[n] = e;
}

// ---------------- CSR scatter: 4 edges/thread, batched atomics --------------
__global__ void scatter_kernel(const int* __restrict__ src,
                               const int* __restrict__ dst, int e) {
    int i = blockIdx.x * blockDim.x + threadIdx.x;
    int q = e >> 2;
    if (i < q) {
        int4 d = ((const int4*)dst)[i];
        int4 s = ((const int4*)src)[i];
        // 4 independent atomics in flight, then 4 stores
        int p0 = atomicAdd(&g_cursor[d.x], 1);
        int p1 = atomicAdd(&g_cursor[d.y], 1);
        int p2 = atomicAdd(&g_cursor[d.z], 1);
        int p3 = atomicAdd(&g_cursor[d.w], 1);
        float n0 = g_norm[s.x], n1 = g_norm[s.y];
        float n2 = g_norm[s.z], n3 = g_norm[s.w];
        g_csredge[p0] = make_uint2((unsigned)(s.x * 16), __float_as_uint(n0));
        g_csredge[p1] = make_uint2((unsigned)(s.y * 16), __float_as_uint(n1));
        g_csredge[p2] = make_uint2((unsigned)(s.z * 16), __float_as_uint(n2));
        g_csredge[p3] = make_uint2((unsigned)(s.w * 16), __float_as_uint(n3));
    }
    if (i == 0) {
        for (int j = q * 4; j < e; j++) {
            int s = src[j];
            int p = atomicAdd(&g_cursor[dst[j]], 1);
            g_csredge[p] = make_uint2((unsigned)(s * 16),
                                      __float_as_uint(g_norm[s]));
        }
    }
}

// ---------------- half-warp-per-node SpMM (uint4 rows, fused edges) ---------
// hout[v] = norm[v] * sum_{s in CSR[v]} norm[s] * hin[s]
__global__ __launch_bounds__(256)
void spmm_kernel(const uint4* __restrict__ hin,
                 uint4* __restrict__ hout, int n) {
    int hw   = threadIdx.x >> 4;          // half-warp slot 0..15
    int node = blockIdx.x * 16 + hw;
    int lane = threadIdx.x & 15;
    if (node >= n) return;
    int beg = g_rowptr[node], end = g_rowptr[node + 1];
    const uint4* hp = hin + lane;         // pre-biased by lane
    float a0 = 0.f, a1 = 0.f, a2 = 0.f, a3 = 0.f;
    float a4 = 0.f, a5 = 0.f, a6 = 0.f, a7 = 0.f;
    #pragma unroll 4
    for (int e = beg; e < end; e++) {
        uint2 em = __ldg(&g_csredge[e]);   // broadcast LDG.64
        uint4 p  = __ldg(&hp[em.x]);       // LDG.128 feature row slice
        float w  = __uint_as_float(em.y);
        float2 f0 = __bfloat1622float2(*(__nv_bfloat162*)&p.x);
        float2 f1 = __bfloat1622float2(*(__nv_bfloat162*)&p.y);
        float2 f2 = __bfloat1622float2(*(__nv_bfloat162*)&p.z);
        float2 f3 = __bfloat1622float2(*(__nv_bfloat162*)&p.w);
        a0 = fmaf(f0.x, w, a0);  a1 = fmaf(f0.y, w, a1);
        a2 = fmaf(f1.x, w, a2);  a3 = fmaf(f1.y, w, a3);
        a4 = fmaf(f2.x, w, a4);  a5 = fmaf(f2.y, w, a5);
        a6 = fmaf(f3.x, w, a6);  a7 = fmaf(f3.y, w, a7);
    }
    float nv = g_norm[node];
    __nv_bfloat162 o0 = __float22bfloat162_rn(make_float2(a0 * nv, a1 * nv));
    __nv_bfloat162 o1 = __float22bfloat162_rn(make_float2(a2 * nv, a3 * nv));
    __nv_bfloat162 o2 = __float22bfloat162_rn(make_float2(a4 * nv, a5 * nv));
    __nv_bfloat162 o3 = __float22bfloat162_rn(make_float2(a6 * nv, a7 * nv));
    hout[node * 16 + lane] = make_uint4(*(unsigned*)&o0, *(unsigned*)&o1,
                                        *(unsigned*)&o2, *(unsigned*)&o3);
}

// ---------------- tensor-core GEMM helpers ----------------------------------
__device__ __forceinline__ void ldsm4(unsigned (&r)[4], unsigned addr) {
    asm volatile("ldmatrix.sync.aligned.m8n8.x4.shared.b16 {%0,%1,%2,%3}, [%4];"
        : "=r"(r[0]), "=r"(r[1]), "=r"(r[2]), "=r"(r[3]) : "r"(addr));
}
__device__ __forceinline__ void ldsm4t(unsigned (&r)[4], unsigned addr) {
    asm volatile("ldmatrix.sync.aligned.m8n8.x4.trans.shared.b16 {%0,%1,%2,%3}, [%4];"
        : "=r"(r[0]), "=r"(r[1]), "=r"(r[2]), "=r"(r[3]) : "r"(addr));
}
__device__ __forceinline__ void mma_bf16(float (&c)[4], const unsigned (&a)[4],
                                         unsigned b0, unsigned b1) {
    asm volatile("mma.sync.aligned.m16n8k16.row.col.f32.bf16.bf16.f32 "
        "{%0,%1,%2,%3}, {%4,%5,%6,%7}, {%8,%9}, {%0,%1,%2,%3};"
        : "+f"(c[0]), "+f"(c[1]), "+f"(c[2]), "+f"(c[3])
        : "r"(a[0]), "r"(a[1]), "r"(a[2]), "r"(a[3]), "r"(b0), "r"(b1));
}

// C = act([A|...] @ Wb) -> bf16x2 packed output.
// Af non-null: A is fp32 (gating path), converted during smem load.
// statacc non-null: fused BN stats (per-col sum / sumsq of pre-rounding fp32).
#define A_STRIDE 56
#define B_STRIDE 136
__global__ __launch_bounds__(256, 2)
void gemm_bf16_kernel(const __nv_bfloat16* __restrict__ A0,
                      const __nv_bfloat16* __restrict__ A1,
                      const __nv_bfloat16* __restrict__ A2,
                      const float* __restrict__ Af,
                      const __nv_bfloat16* __restrict__ Wb,
                      const float* __restrict__ bias,
                      unsigned int* __restrict__ outb,
                      float* __restrict__ statacc,
                      int nrows, int ktiles, int act) {
    __shared__ __align__(16) unsigned short As[128 * A_STRIDE];
    __shared__ __align__(16) unsigned short Bs[32 * B_STRIDE];
    __shared__ float smstat[256];

    int tid  = threadIdx.x;
    int lane = tid & 31;
    int wid  = tid >> 5;
    int m_warp = (wid >> 1) * 32;
    int n_warp = (wid & 1) * 64;
    int r0 = blockIdx.x * 128;

    unsigned as_base = (unsigned)__cvta_generic_to_shared(As);
    unsigned bs_base = (unsigned)__cvta_generic_to_shared(Bs);

    float acc[2][8][4];
    #pragma unroll
    for (int mt = 0; mt < 2; mt++)
        #pragma unroll
        for (int nt = 0; nt < 8; nt++)
            #pragma unroll
            for (int k = 0; k < 4; k++) acc[mt][nt][k] = 0.f;

    for (int kt = 0; kt < ktiles; kt++) {
        int seg = kt >> 2;
        const __nv_bfloat16* Ap = (seg == 0) ? A0 : ((seg == 1) ? A1 : A2);
        int kk = (kt & 3) * 32;

        // A tile [128 x 32] bf16 (convert from fp32 if Af path)
        #pragma unroll
        for (int it = 0; it < 2; it++) {
            int idx = tid + it * 256;
            int row = idx >> 2;
            int ch  = idx & 3;
            int gr  = r0 + row;
            uint4 v = make_uint4(0u, 0u, 0u, 0u);
            if (Af) {
                if (gr < nrows) {
                    float4 u0 = *(const float4*)(Af + gr * 128 + kk + ch * 8);
                    float4 u1 = *(const float4*)(Af + gr * 128 + kk + ch * 8 + 4);
                    __nv_bfloat162 p0 = __float22bfloat162_rn(make_float2(u0.x, u0.y));
                    __nv_bfloat162 p1 = __float22bfloat162_rn(make_float2(u0.z, u0.w));
                    __nv_bfloat162 p2 = __float22bfloat162_rn(make_float2(u1.x, u1.y));
                    __nv_bfloat162 p3 = __float22bfloat162_rn(make_float2(u1.z, u1.w));
                    v = make_uint4(*(unsigned*)&p0, *(unsigned*)&p1,
                                   *(unsigned*)&p2, *(unsigned*)&p3);
                }
            } else if (gr < nrows) {
                v = *(const uint4*)(Ap + gr * 128 + kk + ch * 8);
            }
            *(uint4*)(As + row * A_STRIDE + ch * 8) = v;
        }
        // B tile [32 x 128] bf16
        #pragma unroll
        for (int it = 0; it < 2; it++) {
            int idx = tid + it * 256;
            int row = idx >> 4;
            int ch  = idx & 15;
            uint4 v = *(const uint4*)(Wb + (kt * 32 + row) * 128 + ch * 8);
            *(uint4*)(Bs + row * B_STRIDE + ch * 8) = v;
        }
        __syncthreads();

        #pragma unroll
        for (int ksub = 0; ksub < 2; ksub++) {
            unsigned a[2][4];
            #pragma unroll
            for (int mt = 0; mt < 2; mt++) {
                unsigned addr = as_base +
                    ((m_warp + mt * 16 + (lane & 15)) * A_STRIDE +
                     ksub * 16 + (lane >> 4) * 8) * 2;
                ldsm4(a[mt], addr);
            }
            unsigned b[4][4];
            #pragma unroll
            for (int nt2 = 0; nt2 < 4; nt2++) {
                unsigned addr = bs_base +
                    ((ksub * 16 + (lane & 15)) * B_STRIDE +
                     n_warp + nt2 * 16 + (lane >> 4) * 8) * 2;
                ldsm4t(b[nt2], addr);
            }
            #pragma unroll
            for (int mt = 0; mt < 2; mt++)
                #pragma unroll
                for (int nt = 0; nt < 8; nt++)
                    mma_bf16(acc[mt][nt], a[mt],
                             b[nt >> 1][(nt & 1) * 2],
                             b[nt >> 1][(nt & 1) * 2 + 1]);
        }
        __syncthreads();
    }

    // ---------------- epilogue -------------------------------------------
    int g  = lane >> 2;
    int t4 = lane & 3;
    if (statacc) {
        smstat[tid] = 0.f;
        __syncthreads();
    }
    #pragma unroll
    for (int mt = 0; mt < 2; mt++) {
        int row0 = r0 + m_warp + mt * 16 + g;
        bool v0 = row0 < nrows;
        bool v1 = row0 + 8 < nrows;
        #pragma unroll
        for (int nt = 0; nt < 8; nt++) {
            int col = n_warp + nt * 8 + 2 * t4;
            float c0 = acc[mt][nt][0], c1 = acc[mt][nt][1];
            float c2 = acc[mt][nt][2], c3 = acc[mt][nt][3];
            if (act) {
                float b0 = bias[col], b1 = bias[col + 1];
                c0 = 1.f / (1.f + __expf(-(c0 + b0)));
                c1 = 1.f / (1.f + __expf(-(c1 + b1)));
                c2 = 1.f / (1.f + __expf(-(c2 + b0)));
                c3 = 1.f / (1.f + __expf(-(c3 + b1)));
            }
            if (statacc) {
                float a0 = v0 ? c0 : 0.f, a1 = v0 ? c1 : 0.f;
                float a2 = v1 ? c2 : 0.f, a3 = v1 ? c3 : 0.f;
                float s0 = a0 + a2, s1 = a1 + a3;
                float q0 = a0 * a0 + a2 * a2, q1 = a1 * a1 + a3 * a3;
                #pragma unroll
                for (int m = 4; m < 32; m <<= 1) {
                    s0 += __shfl_xor_sync(0xffffffffu, s0, m);
                    s1 += __shfl_xor_sync(0xffffffffu, s1, m);
                    q0 += __shfl_xor_sync(0xffffffffu, q0, m);
                    q1 += __shfl_xor_sync(0xffffffffu, q1, m);
                }
                if (g == 0) {
                    atomicAdd(&smstat[col], s0);
                    atomicAdd(&smstat[col + 1], s1);
                    atomicAdd(&smstat[128 + col], q0);
                    atomicAdd(&smstat[128 + col + 1], q1);
                }
            }
            if (v0) {
                __nv_bfloat162 p = __float22bfloat162_rn(make_float2(c0, c1));
                outb[row0 * 64 + (col >> 1)] = *(unsigned*)&p;
            }
            if (v1) {
                __nv_bfloat162 p = __float22bfloat162_rn(make_float2(c2, c3));
                outb[(row0 + 8) * 64 + (col >> 1)] = *(unsigned*)&p;
            }
        }
    }
    if (statacc) {
        __syncthreads();
        atomicAdd(&statacc[tid], smstat[tid]);
    }
}

// ---------------- BN apply + ReLU (bf16 z in, optional bf16 out, colsum) ----
__global__ void bn_apply_kernel(const unsigned int* __restrict__ z2,
                                unsigned int* __restrict__ hout2,
                                const float* __restrict__ acc,
                                const float* __restrict__ gamma,
                                const float* __restrict__ beta,
                                int n, int docol) {
    int cp  = threadIdx.x & 63;
    int sub = threadIdx.x >> 6;
    int c0 = cp * 2, c1 = c0 + 1;
    float inv_n = 1.f / (float)n;
    float mu0 = acc[c0] * inv_n, mu1 = acc[c1] * inv_n;
    float va0 = acc[128 + c0] * inv_n - mu0 * mu0;
    float va1 = acc[128 + c1] * inv_n - mu1 * mu1;
    float s0 = rsqrtf(va0 + BN_EPS) * gamma[c0];
    float s1 = rsqrtf(va1 + BN_EPS) * gamma[c1];
    float h0 = beta[c0] - mu0 * s0;
    float h1 = beta[c1] - mu1 * s1;
    int r0 = blockIdx.x * 128;
    int r1 = min(r0 + 128, n);
    float cs0 = 0.f, cs1 = 0.f;
    for (int r = r0 + sub; r < r1; r += 4) {
        unsigned p = z2[r * 64 + cp];
        float2 f = __bfloat1622float2(*(__nv_bfloat162*)&p);
        float v0 = fmaxf(fmaf(f.x, s0, h0), 0.f);
        float v1 = fmaxf(fmaf(f.y, s1, h1), 0.f);
        if (hout2) {
            __nv_bfloat162 o = __float22bfloat162_rn(make_float2(v0, v1));
            hout2[r * 64 + cp] = *(unsigned*)&o;
        }
        cs0 += v0;
        cs1 += v1;
    }
    if (docol) {
        atomicAdd(&g_colsum[c0], cs0);
        atomicAdd(&g_colsum[c1], cs1);
    }
}

// ---------------- readout: out = colmean(h) @ Wd + bd -----------------------
__global__ void final_kernel(const float* __restrict__ Wd,
                             const float* __restrict__ bd,
                             float* __restrict__ out, int n) {
    int j = threadIdx.x;
    float inv_n = 1.f / (float)n;
    float acc = bd[j];
    #pragma unroll 4
    for (int c = 0; c < D; c++)
        acc = fmaf(__ldg(&g_colsum[c]) * inv_n, Wd[c * 256 + j], acc);
    out[j] = acc;
}

// ---------------- launch ----------------------------------------------------
extern "C" void kernel_launch(void* const* d_in, const int* in_sizes, int n_in,
                              void* d_out, int out_size) {
    const float* features = (const float*)d_in[0];
    const int*   src      = (const int*)  d_in[1];
    const int*   dst      = (const int*)  d_in[2];
    const float* Wg  = (const float*)d_in[3];
    const float* bg  = (const float*)d_in[4];
    const float* Wc1 = (const float*)d_in[5];
    const float* g1  = (const float*)d_in[6];
    const float* b1  = (const float*)d_in[7];
    const float* Wc2 = (const float*)d_in[8];
    const float* g2  = (const float*)d_in[9];
    const float* b2  = (const float*)d_in[10];
    const float* Wd  = (const float*)d_in[11];
    const float* bd  = (const float*)d_in[12];
    float* out = (float*)d_out;

    int N = in_sizes[0] / D;
    int E = in_sizes[1];

    void* p;
    __nv_bfloat16 *hb0, *hb1, *hb2, *wb;
    unsigned int* zb;
    float* bnacc;
    cudaGetSymbolAddress(&p, g_hb0);   hb0 = (__nv_bfloat16*)p;
    cudaGetSymbolAddress(&p, g_hb1);   hb1 = (__nv_bfloat16*)p;
    cudaGetSymbolAddress(&p, g_hb2);   hb2 = (__nv_bfloat16*)p;
    cudaGetSymbolAddress(&p, g_wb);    wb  = (__nv_bfloat16*)p;
    cudaGetSymbolAddress(&p, g_zb);    zb  = (unsigned int*)p;
    cudaGetSymbolAddress(&p, g_bnacc); bnacc = (float*)p;

    int gb  = (N + 127) / 128;
    int bnb = (N + 127) / 128;
    int spb = (N + 15) / 16;
    int nsb = (N + 1023) / 1024;
    int eb2 = ((E >> 1) + 255) / 256;
    int eb4 = ((E >> 2) + 255) / 256;

    // fork/join: graph-structure chain on a side stream, concurrent with
    // weight-conversion + gating GEMM on the main stream.
    cudaStream_t s1;
    cudaStreamCreateWithFlags(&s1, cudaStreamNonBlocking);
    cudaEvent_t e0, e1;
    cudaEventCreateWithFlags(&e0, cudaEventDisableTiming);
    cudaEventCreateWithFlags(&e1, cudaEventDisableTiming);

    // fork immediately — setup branch depends on nothing from main
    cudaEventRecord(e0, 0);
    cudaStreamWaitEvent(s1, e0, 0);

    // setup chain on side stream
    zero_deg_kernel<<<(N + 255) / 256, 256, 0, s1>>>(N);
    count_deg_kernel<<<eb2, 256, 0, s1>>>(dst, E);
    scanA_kernel<<<nsb, 1024, 0, s1>>>(N);
    scanC_kernel<<<(N + 255) / 256, 256, 0, s1>>>(N, E, nsb);
    scatter_kernel<<<eb4, 256, 0, s1>>>(src, dst, E);
    cudaEventRecord(e1, s1);

    // main stream: weights/accumulators, then gating GEMM
    init_kernel<<<448, 256>>>(Wg, Wc1, Wc2);
    gemm_bf16_kernel<<<gb, 256>>>(nullptr, nullptr, nullptr, features, wb, bg,
                                  (unsigned int*)hb0, nullptr, N, 4, 1);

    // join: spmm needs both the gating output and the CSR structure
    cudaStreamWaitEvent(0, e1, 0);

    // ---- layer 1 ----
    spmm_kernel<<<spb, 256>>>((const uint4*)hb0, (uint4*)hb1, N);
    spmm_kernel<<<spb, 256>>>((const uint4*)hb1, (uint4*)hb2, N);
    gemm_bf16_kernel<<<gb, 256>>>(hb0, hb1, hb2, nullptr, wb + 16384, nullptr,
                                  zb, bnacc, N, 12, 0);
    bn_apply_kernel<<<bnb, 256>>>(zb, (unsigned int*)hb0, bnacc, g1, b1, N, 0);

    // ---- layer 2 ----
    spmm_kernel<<<spb, 256>>>((const uint4*)hb0, (uint4*)hb1, N);
    spmm_kernel<<<spb, 256>>>((const uint4*)hb1, (uint4*)hb2, N);
    gemm_bf16_kernel<<<gb, 256>>>(hb0, hb1, hb2, nullptr, wb + 65536, nullptr,
                                  zb, bnacc + 256, N, 12, 0);
    bn_apply_kernel<<<bnb, 256>>>(zb, nullptr, bnacc + 256, g2, b2, N, 1);

    // readout
    final_kernel<<<1, 256>>>(Wd, bd, out, N);

    cudaEventDestroy(e0);
    cudaEventDestroy(e1);
    cudaStreamDestroy(s1);
}